// round 7
// baseline (speedup 1.0000x reference)
#include <cuda_runtime.h>
#include <cstdint>
#include <math.h>

// ---------------- problem constants ----------------
static constexpr int BATCH = 4;
static constexpr int C     = 512;
static constexpr int HW    = 4096;
static constexpr int G     = 32;
static constexpr int CPG   = C / G;          // 16
static constexpr size_t CBS = (size_t)C * HW;
static constexpr size_t SBS = (size_t)HW * HW;

// ---------------- scratch ----------------
__device__ float g_hnt[BATCH * HW * C];          // hn transposed [b][hw][c] (tf32-rounded)
__device__ float g_qt [BATCH * HW * C];          // q transposed (tf32-rounded)
__device__ float g_kt [BATCH * HW * C];          // k transposed (tf32-rounded)
__device__ float g_v  [BATCH * C * HW];          // v (tf32-rounded)
__device__ float g_s  [(size_t)BATCH * HW * HW]; // S logits fp32 / probs tf32-rounded
__device__ float g_aot[BATCH * HW * C];          // attn out transposed (tf32-rounded)
__device__ float g_w4 [4 * C * C];               // rounded wq,wk,wv,wproj

// ---------------- helpers ----------------
__device__ __forceinline__ uint32_t f2tf32(float x) {
    uint32_t r;
    asm("cvt.rna.tf32.f32 %0, %1;" : "=r"(r) : "f"(x));
    return r;
}
__device__ __forceinline__ float rnd_tf32(float x) {
    return __uint_as_float(f2tf32(x));
}
__device__ __forceinline__ void cp_async16(uint32_t s, const void* g) {
    asm volatile("cp.async.cg.shared.global [%0], [%1], 16;" :: "r"(s), "l"(g));
}
__device__ __forceinline__ void ldsm_x4(uint32_t& r0, uint32_t& r1, uint32_t& r2,
                                        uint32_t& r3, uint32_t addr) {
    asm volatile("ldmatrix.sync.aligned.m8n8.x4.shared.b16 {%0,%1,%2,%3}, [%4];"
                 : "=r"(r0), "=r"(r1), "=r"(r2), "=r"(r3) : "r"(addr));
}
__device__ __forceinline__ void ldsm_x2(uint32_t& r0, uint32_t& r1, uint32_t addr) {
    asm volatile("ldmatrix.sync.aligned.m8n8.x2.shared.b16 {%0,%1}, [%2];"
                 : "=r"(r0), "=r"(r1) : "r"(addr));
}

// ---------------- round the 4 weight matrices into scratch ----------------
__global__ void round_w_kernel(const float* __restrict__ w0, const float* __restrict__ w1,
                               const float* __restrict__ w2, const float* __restrict__ w3,
                               float* __restrict__ out)
{
    const int which = blockIdx.y;
    const float* src = which == 0 ? w0 : which == 1 ? w1 : which == 2 ? w2 : w3;
    float* dst = out + (size_t)which * C * C;
    const int i = (blockIdx.x * 256 + threadIdx.x) * 4;
    float4 v = *(const float4*)(src + i);
    v.x = rnd_tf32(v.x); v.y = rnd_tf32(v.y);
    v.z = rnd_tf32(v.z); v.w = rnd_tf32(v.w);
    *(float4*)(dst + i) = v;
}

// ---------------- GroupNorm with transposed, tf32-rounded output ----------------
__global__ void groupnorm_t_kernel(const float* __restrict__ x,
                                   const float* __restrict__ scale,
                                   const float* __restrict__ bias,
                                   float* __restrict__ out_t)
{
    const int bg = blockIdx.x;
    const int b = bg / G, g = bg % G;
    const int N = CPG * HW;
    const size_t base = ((size_t)b * C + (size_t)g * CPG) * HW;
    const float* xp = x + base;
    const int t = threadIdx.x;

    float s = 0.f, ss = 0.f;
    for (int i = t; i < N; i += 256) {
        float v = xp[i];
        s += v; ss += v * v;
    }
    __shared__ float sh_s[256], sh_q[256];
    sh_s[t] = s; sh_q[t] = ss;
    __syncthreads();
    for (int o = 128; o > 0; o >>= 1) {
        if (t < o) { sh_s[t] += sh_s[t + o]; sh_q[t] += sh_q[t + o]; }
        __syncthreads();
    }
    const float mean = sh_s[0] * (1.0f / N);
    const float var  = sh_q[0] * (1.0f / N) - mean * mean;
    const float inv  = rsqrtf(var + 1e-6f);

    float scl[16], bia[16];
#pragma unroll
    for (int c = 0; c < 16; c++) {
        scl[c] = scale[g * CPG + c] * inv;
        bia[c] = bias[g * CPG + c] - mean * scl[c];
    }

    for (int chunk = 0; chunk < 16; ++chunk) {
        const int n = chunk * 256 + t;
        float vals[16];
#pragma unroll
        for (int c = 0; c < 16; c++)
            vals[c] = rnd_tf32(xp[c * HW + n] * scl[c] + bia[c]);
        float* op = out_t + ((size_t)b * HW + n) * C + g * CPG;
#pragma unroll
        for (int c4 = 0; c4 < 4; c4++)
            *(float4*)(op + c4 * 4) = *(const float4*)(vals + c4 * 4);
    }
}

// ---------------- row softmax (tf32-rounded probability output) ----------------
__global__ void softmax_kernel(float* __restrict__ sbuf)
{
    const size_t row = blockIdx.x;
    float* p = sbuf + row * (size_t)HW;
    const int t = threadIdx.x;

    float r[16];
    float m = -1e30f;
#pragma unroll
    for (int j = 0; j < 16; j++) { r[j] = p[t + j * 256]; m = fmaxf(m, r[j]); }
    __shared__ float shm[8], shs[8];
#pragma unroll
    for (int o = 16; o > 0; o >>= 1) m = fmaxf(m, __shfl_xor_sync(0xffffffffu, m, o));
    if ((t & 31) == 0) shm[t >> 5] = m;
    __syncthreads();
    m = shm[0];
#pragma unroll
    for (int w = 1; w < 8; w++) m = fmaxf(m, shm[w]);

    float sum = 0.f;
#pragma unroll
    for (int j = 0; j < 16; j++) { r[j] = __expf(r[j] - m); sum += r[j]; }
#pragma unroll
    for (int o = 16; o > 0; o >>= 1) sum += __shfl_xor_sync(0xffffffffu, sum, o);
    if ((t & 31) == 0) shs[t >> 5] = sum;
    __syncthreads();
    sum = shs[0];
#pragma unroll
    for (int w = 1; w < 8; w++) sum += shs[w];
    const float invs = 1.0f / sum;
#pragma unroll
    for (int j = 0; j < 16; j++) p[t + j * 256] = rnd_tf32(r[j] * invs);
}

// =====================================================================
// tf32 mma.sync GEMM; fragment loads via ldmatrix. Inputs pre-rounded.
// D[m][n] = alpha * sum_k A[m][k]*B[n][k] (+bias[m]) (+res)
// TOUT: 0 row-major out, 1 transposed out. RND: round outputs to tf32.
// SWAP: m-tile from blockIdx.x.
// CTA 128x128, BK=16, 256 thr, 8 warps (2m x 4n), warp tile 64x32.
// =====================================================================
template<int TOUT, int SWAP, int RND>
__global__ void __launch_bounds__(256, 2)
gemm_mma(const float* __restrict__ A, const float* __restrict__ B,
         float* __restrict__ Cm, int K,
         int lda, size_t a_bs, int ldb, size_t b_bs, int ldc, size_t c_bs,
         float alpha, const float* __restrict__ bias,
         const float* __restrict__ res, size_t r_bs)
{
    constexpr int STR = 20;
    constexpr uint32_t BUFB = 128 * STR * 4;
    __shared__ float As[2][128 * STR];
    __shared__ float Bs[2][128 * STR];

    const int tid  = threadIdx.x;
    const int wid  = tid >> 5, lane = tid & 31;
    const int gid  = lane >> 2, tid4 = lane & 3;
    const int mbase = (wid & 1) * 64;
    const int nbase = (wid >> 1) * 32;

    int m0, n0;
    if (SWAP) { m0 = blockIdx.x * 128; n0 = blockIdx.y * 128; }
    else      { m0 = blockIdx.y * 128; n0 = blockIdx.x * 128; }
    const float* Ap = A + (size_t)blockIdx.z * a_bs + (size_t)m0 * lda;
    const float* Bp = B + (size_t)blockIdx.z * b_bs + (size_t)n0 * ldb;

    const int lmm = tid >> 2;
    const int lk4 = tid & 3;
    const uint32_t sA = (uint32_t)__cvta_generic_to_shared(&As[0][0]);
    const uint32_t sB = (uint32_t)__cvta_generic_to_shared(&Bs[0][0]);

    // ldmatrix per-lane base addresses (loop-invariant)
    // A x4: matrices {rows0-7,k0-3},{rows8-15,k0-3},{rows0-7,k4-7},{rows8-15,k4-7}
    const int rowA = mbase + (lane & 7) + ((lane >> 3) & 1) * 8;
    const int colA = (lane >> 4) * 4;
    const uint32_t aBase = sA + (uint32_t)(rowA * STR + colA) * 4u;
    // B x2: matrices {n-rows0-7,k0-3},{n-rows0-7,k4-7} (addr lanes 0-15)
    const int rowB = nbase + (lane & 7);
    const int colB = ((lane >> 3) & 1) * 4;
    const uint32_t bBase = sB + (uint32_t)(rowB * STR + colB) * 4u;

    float acc[4][4][4];
#pragma unroll
    for (int i = 0; i < 4; i++)
#pragma unroll
        for (int j = 0; j < 4; j++)
#pragma unroll
            for (int e = 0; e < 4; e++) acc[i][j][e] = 0.f;

    const int niter = K >> 4;

    {
#pragma unroll
        for (int j = 0; j < 2; j++) {
            const int m = lmm + j * 64;
            const uint32_t so = (uint32_t)(m * STR + lk4 * 4) * 4u;
            cp_async16(sA + so, Ap + (size_t)m * lda + lk4 * 4);
            cp_async16(sB + so, Bp + (size_t)m * ldb + lk4 * 4);
        }
        asm volatile("cp.async.commit_group;" ::: "memory");
    }

    for (int it = 0; it < niter; ++it) {
        const uint32_t bufo = (uint32_t)(it & 1) * BUFB;
        asm volatile("cp.async.wait_group 0;" ::: "memory");
        __syncthreads();

        if (it + 1 < niter) {
            const int k0 = (it + 1) << 4;
            const uint32_t bo = (uint32_t)((it + 1) & 1) * BUFB;
#pragma unroll
            for (int j = 0; j < 2; j++) {
                const int m = lmm + j * 64;
                const uint32_t so = bo + (uint32_t)(m * STR + lk4 * 4) * 4u;
                cp_async16(sA + so, Ap + (size_t)m * lda + k0 + lk4 * 4);
                cp_async16(sB + so, Bp + (size_t)m * ldb + k0 + lk4 * 4);
            }
            asm volatile("cp.async.commit_group;" ::: "memory");
        }

#pragma unroll
        for (int s = 0; s < 2; s++) {
            const uint32_t k8o = bufo + (uint32_t)(s * 8) * 4u;
            uint32_t a[4][4], b[4][2];
#pragma unroll
            for (int mf = 0; mf < 4; mf++)
                ldsm_x4(a[mf][0], a[mf][1], a[mf][2], a[mf][3],
                        aBase + k8o + (uint32_t)(mf * 16 * STR) * 4u);
#pragma unroll
            for (int nf = 0; nf < 4; nf++)
                ldsm_x2(b[nf][0], b[nf][1],
                        bBase + k8o + (uint32_t)(nf * 8 * STR) * 4u);
#pragma unroll
            for (int mf = 0; mf < 4; mf++)
#pragma unroll
                for (int nf = 0; nf < 4; nf++) {
                    asm volatile(
                        "mma.sync.aligned.m16n8k8.row.col.f32.tf32.tf32.f32 "
                        "{%0,%1,%2,%3}, {%4,%5,%6,%7}, {%8,%9}, {%0,%1,%2,%3};"
                        : "+f"(acc[mf][nf][0]), "+f"(acc[mf][nf][1]),
                          "+f"(acc[mf][nf][2]), "+f"(acc[mf][nf][3])
                        : "r"(a[mf][0]), "r"(a[mf][1]), "r"(a[mf][2]), "r"(a[mf][3]),
                          "r"(b[nf][0]), "r"(b[nf][1]));
                }
        }
    }

    // ---- epilogue ----
    float* Cp = Cm + (size_t)blockIdx.z * c_bs;
    const float* Rp = res ? (res + (size_t)blockIdx.z * r_bs) : nullptr;
#pragma unroll
    for (int mf = 0; mf < 4; mf++) {
        const int r0 = m0 + mbase + mf * 16 + gid;
        const int r1 = r0 + 8;
        const float bv0 = bias ? bias[r0] : 0.f;
        const float bv1 = bias ? bias[r1] : 0.f;
#pragma unroll
        for (int nf = 0; nf < 4; nf++) {
            const int cb = n0 + nbase + nf * 8 + tid4 * 2;
            float v00 = acc[mf][nf][0] * alpha + bv0;
            float v01 = acc[mf][nf][1] * alpha + bv0;
            float v10 = acc[mf][nf][2] * alpha + bv1;
            float v11 = acc[mf][nf][3] * alpha + bv1;
            if (RND) {
                v00 = rnd_tf32(v00); v01 = rnd_tf32(v01);
                v10 = rnd_tf32(v10); v11 = rnd_tf32(v11);
            }
            if (TOUT) {
                Cp[(size_t)cb * ldc + r0]       = v00;
                Cp[(size_t)(cb + 1) * ldc + r0] = v01;
                Cp[(size_t)cb * ldc + r1]       = v10;
                Cp[(size_t)(cb + 1) * ldc + r1] = v11;
            } else {
                if (Rp) {
                    v00 += Rp[(size_t)r0 * ldc + cb];
                    v01 += Rp[(size_t)r0 * ldc + cb + 1];
                    v10 += Rp[(size_t)r1 * ldc + cb];
                    v11 += Rp[(size_t)r1 * ldc + cb + 1];
                }
                *(float2*)&Cp[(size_t)r0 * ldc + cb] = make_float2(v00, v01);
                *(float2*)&Cp[(size_t)r1 * ldc + cb] = make_float2(v10, v11);
            }
        }
    }
}

// ---------------- launch ----------------
extern "C" void kernel_launch(void* const* d_in, const int* in_sizes, int n_in,
                              void* d_out, int out_size)
{
    const float* x  = (const float*)d_in[0];
    const float* gs = (const float*)d_in[1];
    const float* gb = (const float*)d_in[2];
    const float* wq = (const float*)d_in[3];
    const float* bq = (const float*)d_in[4];
    const float* wk = (const float*)d_in[5];
    const float* bk = (const float*)d_in[6];
    const float* wv = (const float*)d_in[7];
    const float* bv = (const float*)d_in[8];
    const float* wp = (const float*)d_in[9];
    const float* bp = (const float*)d_in[10];
    float* out = (float*)d_out;

    float *hnt, *qt, *kt, *v, *s, *aot, *w4;
    cudaGetSymbolAddress((void**)&hnt, g_hnt);
    cudaGetSymbolAddress((void**)&qt,  g_qt);
    cudaGetSymbolAddress((void**)&kt,  g_kt);
    cudaGetSymbolAddress((void**)&v,   g_v);
    cudaGetSymbolAddress((void**)&s,   g_s);
    cudaGetSymbolAddress((void**)&aot, g_aot);
    cudaGetSymbolAddress((void**)&w4,  g_w4);

    const float* rwq = w4;
    const float* rwk = w4 + (size_t)C * C;
    const float* rwv = w4 + 2 * (size_t)C * C;
    const float* rwp = w4 + 3 * (size_t)C * C;

    const float attn_scale = 1.0f / sqrtf((float)C);

    // 0. round weights to tf32
    {
        dim3 grid(C * C / (256 * 4), 4);
        round_w_kernel<<<grid, 256>>>(wq, wk, wv, wp, w4);
    }

    // 1. GroupNorm -> hn_t [b][hw][c], tf32-rounded
    groupnorm_t_kernel<<<BATCH * G, 256>>>(x, gs, gb, hnt);

    // 2. q_t/k_t = (W @ hn)^T ; v = W @ hn
    {
        dim3 grid(HW / 128, C / 128, BATCH);
        gemm_mma<1, 0, 1><<<grid, 256>>>(rwq, hnt, qt, C,
                                         C, 0, C, CBS, C, CBS, 1.0f, bq, nullptr, 0);
        gemm_mma<1, 0, 1><<<grid, 256>>>(rwk, hnt, kt, C,
                                         C, 0, C, CBS, C, CBS, 1.0f, bk, nullptr, 0);
        gemm_mma<0, 0, 1><<<grid, 256>>>(rwv, hnt, v, C,
                                         C, 0, C, CBS, HW, CBS, 1.0f, bv, nullptr, 0);
    }

    // 3. S logits (fp32)
    {
        dim3 grid(HW / 128, HW / 128, BATCH);
        gemm_mma<0, 0, 0><<<grid, 256>>>(qt, kt, s, C,
                                         C, CBS, C, CBS, HW, SBS,
                                         attn_scale, nullptr, nullptr, 0);
    }

    // 4. softmax rows of S -> tf32-rounded probs
    softmax_kernel<<<BATCH * HW, 256>>>(s);

    // 5. ao_t[b][i][c] = sum_j v[c][j] * P[i][j]
    {
        dim3 grid(C / 128, HW / 128, BATCH);
        gemm_mma<1, 1, 1><<<grid, 256>>>(v, s, aot, HW,
                                         HW, CBS, HW, SBS, C, CBS,
                                         1.0f, nullptr, nullptr, 0);
    }

    // 6. out = wp @ ao + bp + x
    {
        dim3 grid(HW / 128, C / 128, BATCH);
        gemm_mma<0, 0, 0><<<grid, 256>>>(rwp, aot, out, C,
                                         C, 0, C, CBS, HW, CBS,
                                         1.0f, bp, x, CBS);
    }
}

// round 8
// speedup vs baseline: 1.0001x; 1.0001x over previous
#include <cuda_runtime.h>
#include <cstdint>
#include <math.h>

// ---------------- problem constants ----------------
static constexpr int BATCH = 4;
static constexpr int C     = 512;
static constexpr int HW    = 4096;
static constexpr int G     = 32;
static constexpr int CPG   = C / G;          // 16
static constexpr size_t CBS = (size_t)C * HW;
static constexpr size_t SBS = (size_t)HW * HW;

// ---------------- scratch ----------------
__device__ float g_hnt[BATCH * HW * C];          // hn transposed [b][hw][c] (tf32-rounded)
__device__ float g_qt [BATCH * HW * C];          // q transposed (tf32-rounded)
__device__ float g_kt [BATCH * HW * C];          // k transposed (tf32-rounded)
__device__ float g_v  [BATCH * C * HW];          // v (tf32-rounded)
__device__ float g_s  [(size_t)BATCH * HW * HW]; // S logits fp32 / probs tf32-rounded
__device__ float g_aot[BATCH * HW * C];          // attn out transposed (tf32-rounded)
__device__ float g_w4 [4 * C * C];               // rounded wq,wk,wv,wproj

// ---------------- helpers ----------------
__device__ __forceinline__ uint32_t f2tf32(float x) {
    uint32_t r;
    asm("cvt.rna.tf32.f32 %0, %1;" : "=r"(r) : "f"(x));
    return r;
}
__device__ __forceinline__ float rnd_tf32(float x) {
    return __uint_as_float(f2tf32(x));
}
__device__ __forceinline__ void cp_async16(uint32_t s, const void* g) {
    asm volatile("cp.async.cg.shared.global [%0], [%1], 16;" :: "r"(s), "l"(g));
}
__device__ __forceinline__ void ldsm_x4(uint32_t& r0, uint32_t& r1, uint32_t& r2,
                                        uint32_t& r3, uint32_t addr) {
    asm volatile("ldmatrix.sync.aligned.m8n8.x4.shared.b16 {%0,%1,%2,%3}, [%4];"
                 : "=r"(r0), "=r"(r1), "=r"(r2), "=r"(r3) : "r"(addr));
}
__device__ __forceinline__ void ldsm_x2(uint32_t& r0, uint32_t& r1, uint32_t addr) {
    asm volatile("ldmatrix.sync.aligned.m8n8.x2.shared.b16 {%0,%1}, [%2];"
                 : "=r"(r0), "=r"(r1) : "r"(addr));
}

// ---------------- round the 4 weight matrices into scratch ----------------
__global__ void round_w_kernel(const float* __restrict__ w0, const float* __restrict__ w1,
                               const float* __restrict__ w2, const float* __restrict__ w3,
                               float* __restrict__ out)
{
    const int which = blockIdx.y;
    const float* src = which == 0 ? w0 : which == 1 ? w1 : which == 2 ? w2 : w3;
    float* dst = out + (size_t)which * C * C;
    const int i = (blockIdx.x * 256 + threadIdx.x) * 4;
    float4 v = *(const float4*)(src + i);
    v.x = rnd_tf32(v.x); v.y = rnd_tf32(v.y);
    v.z = rnd_tf32(v.z); v.w = rnd_tf32(v.w);
    *(float4*)(dst + i) = v;
}

// ---------------- GroupNorm with transposed, tf32-rounded output ----------------
__global__ void groupnorm_t_kernel(const float* __restrict__ x,
                                   const float* __restrict__ scale,
                                   const float* __restrict__ bias,
                                   float* __restrict__ out_t)
{
    const int bg = blockIdx.x;
    const int b = bg / G, g = bg % G;
    const int N = CPG * HW;
    const size_t base = ((size_t)b * C + (size_t)g * CPG) * HW;
    const float* xp = x + base;
    const int t = threadIdx.x;

    float s = 0.f, ss = 0.f;
    for (int i = t; i < N; i += 256) {
        float v = xp[i];
        s += v; ss += v * v;
    }
    __shared__ float sh_s[256], sh_q[256];
    sh_s[t] = s; sh_q[t] = ss;
    __syncthreads();
    for (int o = 128; o > 0; o >>= 1) {
        if (t < o) { sh_s[t] += sh_s[t + o]; sh_q[t] += sh_q[t + o]; }
        __syncthreads();
    }
    const float mean = sh_s[0] * (1.0f / N);
    const float var  = sh_q[0] * (1.0f / N) - mean * mean;
    const float inv  = rsqrtf(var + 1e-6f);

    float scl[16], bia[16];
#pragma unroll
    for (int c = 0; c < 16; c++) {
        scl[c] = scale[g * CPG + c] * inv;
        bia[c] = bias[g * CPG + c] - mean * scl[c];
    }

    for (int chunk = 0; chunk < 16; ++chunk) {
        const int n = chunk * 256 + t;
        float vals[16];
#pragma unroll
        for (int c = 0; c < 16; c++)
            vals[c] = rnd_tf32(xp[c * HW + n] * scl[c] + bia[c]);
        float* op = out_t + ((size_t)b * HW + n) * C + g * CPG;
#pragma unroll
        for (int c4 = 0; c4 < 4; c4++)
            *(float4*)(op + c4 * 4) = *(const float4*)(vals + c4 * 4);
    }
}

// ---------------- row softmax (tf32-rounded probability output) ----------------
__global__ void softmax_kernel(float* __restrict__ sbuf)
{
    const size_t row = blockIdx.x;
    float* p = sbuf + row * (size_t)HW;
    const int t = threadIdx.x;

    float r[16];
    float m = -1e30f;
#pragma unroll
    for (int j = 0; j < 16; j++) { r[j] = p[t + j * 256]; m = fmaxf(m, r[j]); }
    __shared__ float shm[8], shs[8];
#pragma unroll
    for (int o = 16; o > 0; o >>= 1) m = fmaxf(m, __shfl_xor_sync(0xffffffffu, m, o));
    if ((t & 31) == 0) shm[t >> 5] = m;
    __syncthreads();
    m = shm[0];
#pragma unroll
    for (int w = 1; w < 8; w++) m = fmaxf(m, shm[w]);

    float sum = 0.f;
#pragma unroll
    for (int j = 0; j < 16; j++) { r[j] = __expf(r[j] - m); sum += r[j]; }
#pragma unroll
    for (int o = 16; o > 0; o >>= 1) sum += __shfl_xor_sync(0xffffffffu, sum, o);
    if ((t & 31) == 0) shs[t >> 5] = sum;
    __syncthreads();
    sum = shs[0];
#pragma unroll
    for (int w = 1; w < 8; w++) sum += shs[w];
    const float invs = 1.0f / sum;
#pragma unroll
    for (int j = 0; j < 16; j++) p[t + j * 256] = rnd_tf32(r[j] * invs);
}

// =====================================================================
// tf32 mma.sync GEMM; fragment loads via ldmatrix. Inputs pre-rounded.
// D[m][n] = alpha * sum_k A[m][k]*B[n][k] (+bias[m]) (+res)
// TOUT: 0 row-major out, 1 transposed out. RND: round outputs to tf32.
// SWAP: m-tile from blockIdx.x.
// CTA 128x128, BK=16, 256 thr, 8 warps (2m x 4n), warp tile 64x32.
// =====================================================================
template<int TOUT, int SWAP, int RND>
__global__ void __launch_bounds__(256, 2)
gemm_mma(const float* __restrict__ A, const float* __restrict__ B,
         float* __restrict__ Cm, int K,
         int lda, size_t a_bs, int ldb, size_t b_bs, int ldc, size_t c_bs,
         float alpha, const float* __restrict__ bias,
         const float* __restrict__ res, size_t r_bs)
{
    constexpr int STR = 20;
    constexpr uint32_t BUFB = 128 * STR * 4;
    __shared__ float As[2][128 * STR];
    __shared__ float Bs[2][128 * STR];

    const int tid  = threadIdx.x;
    const int wid  = tid >> 5, lane = tid & 31;
    const int gid  = lane >> 2, tid4 = lane & 3;
    const int mbase = (wid & 1) * 64;
    const int nbase = (wid >> 1) * 32;

    int m0, n0;
    if (SWAP) { m0 = blockIdx.x * 128; n0 = blockIdx.y * 128; }
    else      { m0 = blockIdx.y * 128; n0 = blockIdx.x * 128; }
    const float* Ap = A + (size_t)blockIdx.z * a_bs + (size_t)m0 * lda;
    const float* Bp = B + (size_t)blockIdx.z * b_bs + (size_t)n0 * ldb;

    const int lmm = tid >> 2;
    const int lk4 = tid & 3;
    const uint32_t sA = (uint32_t)__cvta_generic_to_shared(&As[0][0]);
    const uint32_t sB = (uint32_t)__cvta_generic_to_shared(&Bs[0][0]);

    // ldmatrix per-lane base addresses (loop-invariant)
    // A x4: matrices {rows0-7,k0-3},{rows8-15,k0-3},{rows0-7,k4-7},{rows8-15,k4-7}
    const int rowA = mbase + (lane & 7) + ((lane >> 3) & 1) * 8;
    const int colA = (lane >> 4) * 4;
    const uint32_t aBase = sA + (uint32_t)(rowA * STR + colA) * 4u;
    // B x2: matrices {n-rows0-7,k0-3},{n-rows0-7,k4-7} (addr lanes 0-15)
    const int rowB = nbase + (lane & 7);
    const int colB = ((lane >> 3) & 1) * 4;
    const uint32_t bBase = sB + (uint32_t)(rowB * STR + colB) * 4u;

    float acc[4][4][4];
#pragma unroll
    for (int i = 0; i < 4; i++)
#pragma unroll
        for (int j = 0; j < 4; j++)
#pragma unroll
            for (int e = 0; e < 4; e++) acc[i][j][e] = 0.f;

    const int niter = K >> 4;

    {
#pragma unroll
        for (int j = 0; j < 2; j++) {
            const int m = lmm + j * 64;
            const uint32_t so = (uint32_t)(m * STR + lk4 * 4) * 4u;
            cp_async16(sA + so, Ap + (size_t)m * lda + lk4 * 4);
            cp_async16(sB + so, Bp + (size_t)m * ldb + lk4 * 4);
        }
        asm volatile("cp.async.commit_group;" ::: "memory");
    }

    for (int it = 0; it < niter; ++it) {
        const uint32_t bufo = (uint32_t)(it & 1) * BUFB;
        asm volatile("cp.async.wait_group 0;" ::: "memory");
        __syncthreads();

        if (it + 1 < niter) {
            const int k0 = (it + 1) << 4;
            const uint32_t bo = (uint32_t)((it + 1) & 1) * BUFB;
#pragma unroll
            for (int j = 0; j < 2; j++) {
                const int m = lmm + j * 64;
                const uint32_t so = bo + (uint32_t)(m * STR + lk4 * 4) * 4u;
                cp_async16(sA + so, Ap + (size_t)m * lda + k0 + lk4 * 4);
                cp_async16(sB + so, Bp + (size_t)m * ldb + k0 + lk4 * 4);
            }
            asm volatile("cp.async.commit_group;" ::: "memory");
        }

#pragma unroll
        for (int s = 0; s < 2; s++) {
            const uint32_t k8o = bufo + (uint32_t)(s * 8) * 4u;
            uint32_t a[4][4], b[4][2];
#pragma unroll
            for (int mf = 0; mf < 4; mf++)
                ldsm_x4(a[mf][0], a[mf][1], a[mf][2], a[mf][3],
                        aBase + k8o + (uint32_t)(mf * 16 * STR) * 4u);
#pragma unroll
            for (int nf = 0; nf < 4; nf++)
                ldsm_x2(b[nf][0], b[nf][1],
                        bBase + k8o + (uint32_t)(nf * 8 * STR) * 4u);
#pragma unroll
            for (int mf = 0; mf < 4; mf++)
#pragma unroll
                for (int nf = 0; nf < 4; nf++) {
                    asm volatile(
                        "mma.sync.aligned.m16n8k8.row.col.f32.tf32.tf32.f32 "
                        "{%0,%1,%2,%3}, {%4,%5,%6,%7}, {%8,%9}, {%0,%1,%2,%3};"
                        : "+f"(acc[mf][nf][0]), "+f"(acc[mf][nf][1]),
                          "+f"(acc[mf][nf][2]), "+f"(acc[mf][nf][3])
                        : "r"(a[mf][0]), "r"(a[mf][1]), "r"(a[mf][2]), "r"(a[mf][3]),
                          "r"(b[nf][0]), "r"(b[nf][1]));
                }
        }
    }

    // ---- epilogue ----
    float* Cp = Cm + (size_t)blockIdx.z * c_bs;
    const float* Rp = res ? (res + (size_t)blockIdx.z * r_bs) : nullptr;
#pragma unroll
    for (int mf = 0; mf < 4; mf++) {
        const int r0 = m0 + mbase + mf * 16 + gid;
        const int r1 = r0 + 8;
        const float bv0 = bias ? bias[r0] : 0.f;
        const float bv1 = bias ? bias[r1] : 0.f;
#pragma unroll
        for (int nf = 0; nf < 4; nf++) {
            const int cb = n0 + nbase + nf * 8 + tid4 * 2;
            float v00 = acc[mf][nf][0] * alpha + bv0;
            float v01 = acc[mf][nf][1] * alpha + bv0;
            float v10 = acc[mf][nf][2] * alpha + bv1;
            float v11 = acc[mf][nf][3] * alpha + bv1;
            if (RND) {
                v00 = rnd_tf32(v00); v01 = rnd_tf32(v01);
                v10 = rnd_tf32(v10); v11 = rnd_tf32(v11);
            }
            if (TOUT) {
                Cp[(size_t)cb * ldc + r0]       = v00;
                Cp[(size_t)(cb + 1) * ldc + r0] = v01;
                Cp[(size_t)cb * ldc + r1]       = v10;
                Cp[(size_t)(cb + 1) * ldc + r1] = v11;
            } else {
                if (Rp) {
                    v00 += Rp[(size_t)r0 * ldc + cb];
                    v01 += Rp[(size_t)r0 * ldc + cb + 1];
                    v10 += Rp[(size_t)r1 * ldc + cb];
                    v11 += Rp[(size_t)r1 * ldc + cb + 1];
                }
                *(float2*)&Cp[(size_t)r0 * ldc + cb] = make_float2(v00, v01);
                *(float2*)&Cp[(size_t)r1 * ldc + cb] = make_float2(v10, v11);
            }
        }
    }
}

// ---------------- launch ----------------
extern "C" void kernel_launch(void* const* d_in, const int* in_sizes, int n_in,
                              void* d_out, int out_size)
{
    const float* x  = (const float*)d_in[0];
    const float* gs = (const float*)d_in[1];
    const float* gb = (const float*)d_in[2];
    const float* wq = (const float*)d_in[3];
    const float* bq = (const float*)d_in[4];
    const float* wk = (const float*)d_in[5];
    const float* bk = (const float*)d_in[6];
    const float* wv = (const float*)d_in[7];
    const float* bv = (const float*)d_in[8];
    const float* wp = (const float*)d_in[9];
    const float* bp = (const float*)d_in[10];
    float* out = (float*)d_out;

    float *hnt, *qt, *kt, *v, *s, *aot, *w4;
    cudaGetSymbolAddress((void**)&hnt, g_hnt);
    cudaGetSymbolAddress((void**)&qt,  g_qt);
    cudaGetSymbolAddress((void**)&kt,  g_kt);
    cudaGetSymbolAddress((void**)&v,   g_v);
    cudaGetSymbolAddress((void**)&s,   g_s);
    cudaGetSymbolAddress((void**)&aot, g_aot);
    cudaGetSymbolAddress((void**)&w4,  g_w4);

    const float* rwq = w4;
    const float* rwk = w4 + (size_t)C * C;
    const float* rwv = w4 + 2 * (size_t)C * C;
    const float* rwp = w4 + 3 * (size_t)C * C;

    const float attn_scale = 1.0f / sqrtf((float)C);

    // 0. round weights to tf32
    {
        dim3 grid(C * C / (256 * 4), 4);
        round_w_kernel<<<grid, 256>>>(wq, wk, wv, wp, w4);
    }

    // 1. GroupNorm -> hn_t [b][hw][c], tf32-rounded
    groupnorm_t_kernel<<<BATCH * G, 256>>>(x, gs, gb, hnt);

    // 2. q_t/k_t = (W @ hn)^T ; v = W @ hn
    {
        dim3 grid(HW / 128, C / 128, BATCH);
        gemm_mma<1, 0, 1><<<grid, 256>>>(rwq, hnt, qt, C,
                                         C, 0, C, CBS, C, CBS, 1.0f, bq, nullptr, 0);
        gemm_mma<1, 0, 1><<<grid, 256>>>(rwk, hnt, kt, C,
                                         C, 0, C, CBS, C, CBS, 1.0f, bk, nullptr, 0);
        gemm_mma<0, 0, 1><<<grid, 256>>>(rwv, hnt, v, C,
                                         C, 0, C, CBS, HW, CBS, 1.0f, bv, nullptr, 0);
    }

    // 3. S logits (fp32)
    {
        dim3 grid(HW / 128, HW / 128, BATCH);
        gemm_mma<0, 0, 0><<<grid, 256>>>(qt, kt, s, C,
                                         C, CBS, C, CBS, HW, SBS,
                                         attn_scale, nullptr, nullptr, 0);
    }

    // 4. softmax rows of S -> tf32-rounded probs
    softmax_kernel<<<BATCH * HW, 256>>>(s);

    // 5. ao_t[b][i][c] = sum_j v[c][j] * P[i][j]
    {
        dim3 grid(C / 128, HW / 128, BATCH);
        gemm_mma<1, 1, 1><<<grid, 256>>>(v, s, aot, HW,
                                         HW, CBS, HW, SBS, C, CBS,
                                         1.0f, nullptr, nullptr, 0);
    }

    // 6. out = wp @ ao + bp + x
    {
        dim3 grid(HW / 128, C / 128, BATCH);
        gemm_mma<0, 0, 0><<<grid, 256>>>(rwp, aot, out, C,
                                         C, 0, C, CBS, HW, CBS,
                                         1.0f, bp, x, CBS);
    }
}